// round 13
// baseline (speedup 1.0000x reference)
#include <cuda_runtime.h>
#include <cstdint>

#define N_NODES 12288
#define H_DIM   128
#define E_EDGES 393216
#define NEGVAL  (-1000000000.0f)
#define ROW4    (N_NODES / 4)          // 3072 float4 per row
#define ROW_BYTES (N_NODES * 4)        // 49152 bytes per row
#define CAP     256                    // bucket capacity (Poisson(32), max~65)

#define D_GRID    296                  // 148 SMs x 2 blocks (96KB smem each)
#define D_THREADS 512

// Static scratch. g_cursor zero-init; self-restored by D each launch.
__device__ float g_d1[N_NODES];
__device__ float g_d2[N_NODES];
__device__ int   g_cursor[N_NODES];
__device__ int2  g_bucket[(size_t)N_NODES * CAP];  // (src_col, float_bits(value))

// ---------------------------------------------------------------------------
// A1: per-node dots. 1 warp/node, 1 float4 load per lane (R8-proven, 5.9us).
// ---------------------------------------------------------------------------
__global__ void dots_kernel(const float* __restrict__ h,
                            const float* __restrict__ W) {
    int t    = (int)(blockIdx.x * blockDim.x + threadIdx.x);
    int gw   = t >> 5;
    int lane = t & 31;
    if (gw >= N_NODES) return;

    const float4* hr4 = (const float4*)(h + (size_t)gw * H_DIM);
    const float4* w14 = (const float4*)(W);
    const float4* w24 = (const float4*)(W + H_DIM);
    float4 hv = __ldg(&hr4[lane]);
    float4 w1 = __ldg(&w14[lane]);
    float4 w2 = __ldg(&w24[lane]);
    float s1 = fmaf(hv.x, w1.x, fmaf(hv.y, w1.y, fmaf(hv.z, w1.z, hv.w * w1.w)));
    float s2 = fmaf(hv.x, w2.x, fmaf(hv.y, w2.y, fmaf(hv.z, w2.z, hv.w * w2.w)));
#pragma unroll
    for (int off = 16; off; off >>= 1) {
        s1 += __shfl_down_sync(0xffffffffu, s1, off);
        s2 += __shfl_down_sync(0xffffffffu, s2, off);
    }
    if (lane == 0) { g_d1[gw] = s1; g_d2[gw] = s2; }
}

// ---------------------------------------------------------------------------
// A2: place edges with precomputed values, ILP x4 (R9-proven). PDL: edge
//     loads + cursor atomics run pre-sync (independent of A1).
// ---------------------------------------------------------------------------
__global__ void place_kernel(const int*   __restrict__ src,
                             const int*   __restrict__ dst,
                             const float* __restrict__ wts,
                             const float* __restrict__ W,
                             const float* __restrict__ b) {
    int t  = (int)(blockIdx.x * blockDim.x + threadIdx.x);
    int e0 = t * 4;
    if (e0 >= E_EDGES) return;          // E multiple of 4

    int4   s4 = *(const int4*)  (src + e0);
    int4   d4 = *(const int4*)  (dst + e0);
    float4 w4 = *(const float4*)(wts + e0);
    float wlin = __ldg(&W[2 * H_DIM]);
    float bias = __ldg(&b[0]);

    int p0 = atomicAdd(&g_cursor[d4.x], 1);
    int p1 = atomicAdd(&g_cursor[d4.y], 1);
    int p2 = atomicAdd(&g_cursor[d4.z], 1);
    int p3 = atomicAdd(&g_cursor[d4.w], 1);

    cudaGridDependencySynchronize();    // wait for A1's d1/d2

    float a0 = g_d1[d4.x], a1 = g_d1[d4.y], a2 = g_d1[d4.z], a3 = g_d1[d4.w];
    float c0 = g_d2[s4.x], c1 = g_d2[s4.y], c2 = g_d2[s4.z], c3 = g_d2[s4.w];

    float v0 = a0 + c0 + fmaf(w4.x, wlin, bias);
    float v1 = a1 + c1 + fmaf(w4.y, wlin, bias);
    float v2 = a2 + c2 + fmaf(w4.z, wlin, bias);
    float v3 = a3 + c3 + fmaf(w4.w, wlin, bias);

    if (p0 < CAP) g_bucket[(size_t)d4.x * CAP + p0] = make_int2(s4.x, __float_as_int(v0));
    if (p1 < CAP) g_bucket[(size_t)d4.y * CAP + p1] = make_int2(s4.y, __float_as_int(v1));
    if (p2 < CAP) g_bucket[(size_t)d4.z * CAP + p2] = make_int2(s4.z, __float_as_int(v2));
    if (p3 < CAP) g_bucket[(size_t)d4.w * CAP + p3] = make_int2(s4.w, __float_as_int(v3));
}

// ---------------------------------------------------------------------------
// TMA bulk-store helpers (1D smem -> gmem, bulk_group).
// ---------------------------------------------------------------------------
__device__ __forceinline__ void tma_store_row(void* gdst, unsigned ssrc) {
    asm volatile("cp.async.bulk.global.shared::cta.bulk_group [%0], [%1], %2;"
                 :: "l"(gdst), "r"(ssrc), "r"((unsigned)ROW_BYTES) : "memory");
    asm volatile("cp.async.bulk.commit_group;" ::: "memory");
}
template <int NLeft>
__device__ __forceinline__ void tma_wait() {
    asm volatile("cp.async.bulk.wait_group %0;" :: "n"(NLeft) : "memory");
}

// ---------------------------------------------------------------------------
// D: double-buffered fill + merge + TMA bulk store.
//    Two 48KB smem buffers; while buffer P's 48KB bulk store is in flight,
//    buffer !P is filled+merged. No per-thread store loop; the SM only
//    writes smem. Cursor self-reset preserved (deterministic replays).
// ---------------------------------------------------------------------------
__global__ __launch_bounds__(D_THREADS, 2)
void fill_merge_tma_kernel(float* __restrict__ out) {
    extern __shared__ float4 sbuf[];             // 2 x ROW4 float4 = 96KB
    const float4 v  = make_float4(NEGVAL, NEGVAL, NEGVAL, NEGVAL);
    const int    tid = threadIdx.x;

    // PDL pre-sync: prefill buffer 0 (touches no global state).
#pragma unroll
    for (int i = tid; i < ROW4; i += D_THREADS) sbuf[i] = v;

    cudaGridDependencySynchronize();             // buckets + cursors ready

    int parity = 0;
    bool first = true;
    for (int r = blockIdx.x; r < N_NODES; r += D_GRID) {
        float4* buf = sbuf + parity * ROW4;

        // Ensure the store that last used this buffer has drained
        // (<=1 group outstanding means the older one is done).
        if (tid == 0) tma_wait<1>();
        __syncthreads();

        // broadcast count read (hidden under fill)
        int c   = g_cursor[r];
        int cnt = (c < CAP) ? c : CAP;

        if (!first || parity != 0) {             // buffer 0 prefilled pre-sync
#pragma unroll
            for (int i = tid; i < ROW4; i += D_THREADS) buf[i] = v;
        }
        first = false;
        __syncthreads();                         // all cursor[r] reads done

        if (tid == 0) g_cursor[r] = 0;           // self-restore for next launch

        float* buff = (float*)buf;
        const int2* bkt = &g_bucket[(size_t)r * CAP];
        for (int i = tid; i < cnt; i += D_THREADS) {
            int2 ev = bkt[i];
            buff[ev.x] = __int_as_float(ev.y);   // dup races benign
        }
        // make generic-proxy smem writes visible to the async (TMA) proxy
        asm volatile("fence.proxy.async.shared::cta;" ::: "memory");
        __syncthreads();

        if (tid == 0) {
            unsigned saddr = (unsigned)__cvta_generic_to_shared(buf);
            tma_store_row(out + (size_t)r * N_NODES, saddr);
        }
        parity ^= 1;
    }

    // drain outstanding stores before exit
    if (tid == 0) tma_wait<0>();
}

// ---------------------------------------------------------------------------
// Launch. Input order (metadata): h, sources, dests, weights, W, b
// ---------------------------------------------------------------------------
extern "C" void kernel_launch(void* const* d_in, const int* in_sizes, int n_in,
                              void* d_out, int out_size) {
    const float* h       = (const float*)d_in[0];
    const int*   sources = (const int*)  d_in[1];
    const int*   dests   = (const int*)  d_in[2];
    const float* weights = (const float*)d_in[3];
    const float* W       = (const float*)d_in[4];
    const float* b       = (const float*)d_in[5];
    float*       out     = (float*)d_out;

    static int attr_done = 0;                    // host-side, idempotent attr set
    if (!attr_done) {
        cudaFuncSetAttribute(fill_merge_tma_kernel,
                             cudaFuncAttributeMaxDynamicSharedMemorySize,
                             2 * ROW_BYTES);
        attr_done = 1;
    }

    // A1: dots (plain launch; serializes vs previous replay's D).
    dots_kernel<<<(N_NODES * 32) / 256, 256>>>(h, W);

    cudaLaunchAttribute pdl[1];
    pdl[0].id = cudaLaunchAttributeProgrammaticStreamSerialization;
    pdl[0].val.programmaticStreamSerializationAllowed = 1;

    // A2: place (PDL over A1).
    {
        cudaLaunchConfig_t cfg = {};
        cfg.gridDim  = dim3((E_EDGES / 4) / 256);
        cfg.blockDim = dim3(256);
        cfg.attrs    = pdl;
        cfg.numAttrs = 1;
        cudaLaunchKernelEx(&cfg, place_kernel, sources, dests, weights, W, b);
    }

    // D: TMA double-buffered fill+merge (PDL over A2). 2 blocks/SM, one wave.
    {
        cudaLaunchConfig_t cfg = {};
        cfg.gridDim  = dim3(D_GRID);
        cfg.blockDim = dim3(D_THREADS);
        cfg.dynamicSmemBytes = 2 * ROW_BYTES;
        cfg.attrs    = pdl;
        cfg.numAttrs = 1;
        cudaLaunchKernelEx(&cfg, fill_merge_tma_kernel, (float*)out);
    }
}